// round 8
// baseline (speedup 1.0000x reference)
#include <cuda_runtime.h>
#include <cuda_fp16.h>
#include <math.h>
#include <stdint.h>

#define NN 50000
#define EE 800000
#define C0 32
#define C1 64
#define KP 25
#define KGRP 5
#define FIN 160
#define YSTRIDE (KP * 64)   // 1600

// ---------------- scratch -----------------------------------------------------
__device__ __align__(16) __half g_Yh[(size_t)NN * YSTRIDE];  // 160 MB fp16
__device__ __align__(16) float  g_H1[(size_t)NN * 64];
__device__ __align__(16) float  g_H2[(size_t)NN * 64];
__device__ __align__(16) float  g_AGG[(size_t)NN * 64];
__device__ __align__(16) float  g_DEG[NN];                   // 1/max(deg,1) after recip
__device__ __align__(16) float4 g_B[EE];
__device__ int    g_K0[EE];
__device__ int    g_src[EE];
__device__ int    g_dst[EE];

// ---------------- init / prep / recip ----------------------------------------
__global__ void init_kernel() {
    int i = blockIdx.x * blockDim.x + threadIdx.x;
    if (i < NN * 64) g_AGG[i] = 0.0f;
    if (i < NN)      g_DEG[i] = 0.0f;
}

__global__ void prep_kernel(const int* __restrict__ ei,
                            const float* __restrict__ ea) {
    int e = blockIdx.x * blockDim.x + threadIdx.x;
    if (e >= EE) return;
    int dst = ei[EE + e];
    g_src[e] = ei[e];
    g_dst[e] = dst;
    atomicAdd(&g_DEG[dst], 1.0f);
    float v0 = ea[2 * e + 0] * 4.0f;
    float v1 = ea[2 * e + 1] * 4.0f;
    float b0f = floorf(v0), b1f = floorf(v1);
    float f0 = v0 - b0f, f1 = v1 - b1f;
    int i0 = min((int)b0f, 3);
    int i1 = min((int)b1f, 3);
    g_K0[e] = i0 + 5 * i1;
    g_B[e] = make_float4((1.f - f0) * (1.f - f1),
                         f0 * (1.f - f1),
                         (1.f - f0) * f1,
                         f0 * f1);
}

__global__ void recip_kernel() {
    int i = blockIdx.x * blockDim.x + threadIdx.x;
    if (i < NN) g_DEG[i] = 1.0f / fmaxf(g_DEG[i], 1.0f);
}

// ---------------- mma / ldmatrix helpers -------------------------------------
__device__ __forceinline__ uint32_t pack_h2(float a, float b) {
    uint32_t r;
    asm("cvt.rn.f16x2.f32 %0, %1, %2;" : "=r"(r) : "f"(b), "f"(a));
    return r;
}

__device__ __forceinline__ void mma_f16(float c[4], const uint32_t a[4],
                                        const uint32_t b[2]) {
    asm volatile(
        "mma.sync.aligned.m16n8k16.row.col.f32.f16.f16.f32 "
        "{%0,%1,%2,%3}, {%4,%5,%6,%7}, {%8,%9}, {%0,%1,%2,%3};\n"
        : "+f"(c[0]), "+f"(c[1]), "+f"(c[2]), "+f"(c[3])
        : "r"(a[0]), "r"(a[1]), "r"(a[2]), "r"(a[3]),
          "r"(b[0]), "r"(b[1]));
}

__device__ __forceinline__ void ldsm_x4(uint32_t r[4], uint32_t addr) {
    asm volatile("ldmatrix.sync.aligned.m8n8.x4.shared.b16 {%0,%1,%2,%3}, [%4];"
                 : "=r"(r[0]), "=r"(r[1]), "=r"(r[2]), "=r"(r[3]) : "r"(addr));
}

__device__ __forceinline__ void ldsm_x2t(uint32_t r[2], uint32_t addr) {
    asm volatile("ldmatrix.sync.aligned.m8n8.x2.trans.shared.b16 {%0,%1}, [%2];"
                 : "=r"(r[0]), "=r"(r[1]) : "r"(addr));
}

// ---------------- Y = X @ W[k], k split over grid.y, double-buffered Ws ------
// grid: (ceil(N/128), KP/KGRP); 256 threads = 8 warps (4M x 2N).
// A fragments in registers for all KGRP ks; one __syncthreads per k.
template <int CIN>
__global__ void __launch_bounds__(256)
gemm_y_h(const float* __restrict__ X, const float* __restrict__ W) {
    constexpr int SW  = CIN / 2 + 4;   // Xs word stride (80/144 B, 16B-mult)
    constexpr int WSW = 36;            // Ws word stride: 144 B (16B-mult)
    constexpr int KS  = CIN / 16;
    constexpr int NJ  = CIN / 16;      // float4 W-prefetch regs per thread
    __shared__ uint32_t Xs[128 * SW];
    __shared__ uint32_t Ws[2][CIN * WSW];

    const int tid  = threadIdx.x;
    const int lane = tid & 31;
    const int wid  = tid >> 5;
    const int gid  = lane >> 2;
    const int tig  = lane & 3;
    const int rowB = (wid >> 1) * 32;
    const int colB = (wid & 1) * 32;
    const int n0   = blockIdx.x * 128;
    const int kb   = blockIdx.y * KGRP;

    // ---- X tile -> smem (fp16) ----
    for (int i = tid; i < 128 * (CIN / 4); i += 256) {
        int r  = i / (CIN / 4);
        int c4 = (i % (CIN / 4)) * 4;
        float4 v = make_float4(0.f, 0.f, 0.f, 0.f);
        if (n0 + r < NN)
            v = __ldg((const float4*)(X + (size_t)(n0 + r) * CIN + c4));
        *(uint2*)&Xs[r * SW + c4 / 2] =
            make_uint2(pack_h2(v.x, v.y), pack_h2(v.z, v.w));
    }
    // ---- prefetch W[kb] ----
    float4 wreg[NJ];
    {
        const float4* Wp = (const float4*)(W + (size_t)kb * CIN * 64);
        #pragma unroll
        for (int j = 0; j < NJ; j++) wreg[j] = __ldg(Wp + tid + j * 256);
    }
    __syncthreads();

    // ---- A fragments once ----
    uint32_t a[2][KS][4];
    #pragma unroll
    for (int mt = 0; mt < 2; mt++)
        #pragma unroll
        for (int ks = 0; ks < KS; ks++) {
            int m  = rowB + mt * 16 + (lane & 15);
            int kw = ks * 8 + (lane >> 4) * 4;
            uint32_t addr = (uint32_t)__cvta_generic_to_shared(&Xs[m * SW + kw]);
            ldsm_x4(a[mt][ks], addr);
        }

    // ---- prologue: store W[kb] to buf0, prefetch W[kb+1] ----
    #pragma unroll
    for (int j = 0; j < NJ; j++) {
        int lin = (tid + j * 256) * 4;
        int kin = lin / 64, nn = lin % 64;
        float4 v = wreg[j];
        *(uint2*)&Ws[0][kin * WSW + nn / 2] =
            make_uint2(pack_h2(v.x, v.y), pack_h2(v.z, v.w));
    }
    {
        const float4* Wp = (const float4*)(W + (size_t)(kb + 1) * CIN * 64);
        #pragma unroll
        for (int j = 0; j < NJ; j++) wreg[j] = __ldg(Wp + tid + j * 256);
    }
    __syncthreads();

    // ---- k loop (one sync per iter) ----
    #pragma unroll
    for (int kk = 0; kk < KGRP; kk++) {
        const int k = kb + kk;
        // store next W slice into the other buffer
        if (kk + 1 < KGRP) {
            #pragma unroll
            for (int j = 0; j < NJ; j++) {
                int lin = (tid + j * 256) * 4;
                int kin = lin / 64, nn = lin % 64;
                float4 v = wreg[j];
                *(uint2*)&Ws[(kk + 1) & 1][kin * WSW + nn / 2] =
                    make_uint2(pack_h2(v.x, v.y), pack_h2(v.z, v.w));
            }
            if (kk + 2 < KGRP) {
                const float4* Wp = (const float4*)(W + (size_t)(k + 2) * CIN * 64);
                #pragma unroll
                for (int j = 0; j < NJ; j++) wreg[j] = __ldg(Wp + tid + j * 256);
            }
        }

        float c[2][4][4];
        #pragma unroll
        for (int mt = 0; mt < 2; mt++)
            #pragma unroll
            for (int nt = 0; nt < 4; nt++)
                #pragma unroll
                for (int q = 0; q < 4; q++) c[mt][nt][q] = 0.f;

        const uint32_t* wbuf = Ws[kk & 1];
        #pragma unroll
        for (int nt = 0; nt < 4; nt++) {
            #pragma unroll
            for (int ks = 0; ks < KS; ks++) {
                uint32_t b[2];
                int kr = ks * 16 + (lane & 15);
                uint32_t addr = (uint32_t)__cvta_generic_to_shared(
                    &wbuf[kr * WSW + (colB + nt * 8) / 2]);
                ldsm_x2t(b, addr);
                mma_f16(c[0][nt], a[0][ks], b);
                mma_f16(c[1][nt], a[1][ks], b);
            }
        }

        // store fp16 C
        #pragma unroll
        for (int mt = 0; mt < 2; mt++) {
            int row = n0 + rowB + mt * 16 + gid;
            #pragma unroll
            for (int nt = 0; nt < 4; nt++) {
                int col = k * 64 + colB + nt * 8 + 2 * tig;
                if (row < NN)
                    *(uint32_t*)&g_Yh[(size_t)row * YSTRIDE + col] =
                        pack_h2(c[mt][nt][0], c[mt][nt][1]);
                if (row + 8 < NN)
                    *(uint32_t*)&g_Yh[(size_t)(row + 8) * YSTRIDE + col] =
                        pack_h2(c[mt][nt][2], c[mt][nt][3]);
            }
        }
        __syncthreads();
    }
}

// ---------------- per-edge gather (fp16 Y) + combine*1/deg + RED scatter -----
__global__ void edge_kernel() {
    int t = blockIdx.x * blockDim.x + threadIdx.x;
    int e = t >> 4;
    int lane = t & 15;
    if (e >= EE) return;

    int src = g_src[e];
    int dst = g_dst[e];
    int k0  = g_K0[e];
    float4 b = g_B[e];
    float inv = __ldg(&g_DEG[dst]);   // broadcast within the 16-lane group

    const uint2* base = (const uint2*)(g_Yh + (size_t)src * YSTRIDE + k0 * 64);
    uint2 q0 = __ldg(base + lane);        // row k0
    uint2 q1 = __ldg(base + 16 + lane);   // row k0+1
    uint2 q2 = __ldg(base + 80 + lane);   // row k0+5
    uint2 q3 = __ldg(base + 96 + lane);   // row k0+6

    float2 a0 = __half22float2(*(__half2*)&q0.x), a1 = __half22float2(*(__half2*)&q0.y);
    float2 b0 = __half22float2(*(__half2*)&q1.x), b1 = __half22float2(*(__half2*)&q1.y);
    float2 c0 = __half22float2(*(__half2*)&q2.x), c1 = __half22float2(*(__half2*)&q2.y);
    float2 d0 = __half22float2(*(__half2*)&q3.x), d1 = __half22float2(*(__half2*)&q3.y);

    float4 m;
    m.x = (b.x * a0.x + b.y * b0.x + b.z * c0.x + b.w * d0.x) * inv;
    m.y = (b.x * a0.y + b.y * b0.y + b.z * c0.y + b.w * d0.y) * inv;
    m.z = (b.x * a1.x + b.y * b1.x + b.z * c1.x + b.w * d1.x) * inv;
    m.w = (b.x * a1.y + b.y * b1.y + b.z * c1.y + b.w * d1.y) * inv;

    float* dptr = g_AGG + (size_t)dst * 64 + lane * 4;
    asm volatile("red.global.add.v4.f32 [%0], {%1, %2, %3, %4};"
                 :: "l"(dptr), "f"(m.x), "f"(m.y), "f"(m.z), "f"(m.w)
                 : "memory");
}

// ---------------- finalize: agg + root GEMM + bias + relu + re-zero AGG -----
template <int CIN>
__global__ void finalize_kernel(const float* __restrict__ X,
                                const float* __restrict__ root,
                                const float* __restrict__ bias,
                                float* __restrict__ H) {
    __shared__ __align__(16) float rs[CIN * 64];
    __shared__ __align__(16) float xs[8][CIN];
    const int tid = threadIdx.x;

    for (int i = tid; i < CIN * 16; i += 512)
        ((float4*)rs)[i] = __ldg(((const float4*)root) + i);

    const int n0 = blockIdx.x * 8;
    for (int i = tid; i < 8 * CIN / 4; i += 512) {
        int lin = i * 4;
        int r = lin / CIN, c = lin % CIN;
        int n = n0 + r;
        float4 v = make_float4(0.f, 0.f, 0.f, 0.f);
        if (n < NN) v = __ldg((const float4*)(X + (size_t)n * CIN + c));
        *(float4*)&xs[r][c] = v;
    }
    __syncthreads();

    const int ln = tid >> 6;
    const int o  = tid & 63;
    const int n  = n0 + ln;
    if (n >= NN) return;

    float acc = 0.f;
    #pragma unroll
    for (int i = 0; i < CIN; i++)
        acc = fmaf(xs[ln][i], rs[i * 64 + o], acc);

    size_t ai = (size_t)n * 64 + o;
    float v = g_AGG[ai] + acc + __ldg(bias + o);
    g_AGG[ai] = 0.0f;
    H[ai] = fmaxf(v, 0.0f);
}

// ---------------- final: concat(x,h1,h2) @ fw + fb --------------------------
__global__ void final_kernel(const float* __restrict__ X,
                             const float* __restrict__ fw,
                             const float* __restrict__ fb,
                             float* __restrict__ out) {
    __shared__ __align__(16) float ws[FIN * 64];
    __shared__ __align__(16) float xs[8][FIN];
    const int tid = threadIdx.x;

    for (int i = tid; i < FIN * 16; i += 512)
        ((float4*)ws)[i] = __ldg(((const float4*)fw) + i);

    const int n0 = blockIdx.x * 8;
    for (int i = tid; i < 8 * FIN / 4; i += 512) {
        int lin = i * 4;
        int r = lin / FIN, c = lin % FIN;
        int n = n0 + r;
        float4 v = make_float4(0.f, 0.f, 0.f, 0.f);
        if (n < NN) {
            if (c < 32)      v = __ldg((const float4*)(X    + (size_t)n * 32 + c));
            else if (c < 96) v = __ldg((const float4*)(g_H1 + (size_t)n * 64 + (c - 32)));
            else             v = __ldg((const float4*)(g_H2 + (size_t)n * 64 + (c - 96)));
        }
        *(float4*)&xs[r][c] = v;
    }
    __syncthreads();

    const int ln = tid >> 6;
    const int o  = tid & 63;
    const int n  = n0 + ln;
    if (n >= NN) return;

    float acc = __ldg(fb + o);
    #pragma unroll
    for (int i = 0; i < FIN; i++)
        acc = fmaf(xs[ln][i], ws[i * 64 + o], acc);
    out[(size_t)n * 64 + o] = acc;
}

// ---------------- launch -----------------------------------------------------
extern "C" void kernel_launch(void* const* d_in, const int* in_sizes, int n_in,
                              void* d_out, int out_size) {
    const float* x     = (const float*)d_in[0];
    const int*   ei    = (const int*)d_in[1];     // int32 (jax x64 disabled)
    const float* ea    = (const float*)d_in[2];
    const float* w0    = (const float*)d_in[3];
    const float* root0 = (const float*)d_in[4];
    const float* b0    = (const float*)d_in[5];
    const float* w1    = (const float*)d_in[6];
    const float* root1 = (const float*)d_in[7];
    const float* b1    = (const float*)d_in[8];
    const float* fw    = (const float*)d_in[9];
    const float* fb    = (const float*)d_in[10];
    float*       out   = (float*)d_out;

    float *h1p, *h2p;
    cudaGetSymbolAddress((void**)&h1p, g_H1);
    cudaGetSymbolAddress((void**)&h2p, g_H2);

    const int zgrid = (NN * 64 + 255) / 256;
    dim3 ggrid((NN + 127) / 128, KP / KGRP);
    const int egrid = (EE * 16 + 255) / 256;
    const int fgrid = (NN + 7) / 8;

    init_kernel<<<zgrid, 256>>>();
    prep_kernel<<<(EE + 255) / 256, 256>>>(ei, ea);
    recip_kernel<<<(NN + 255) / 256, 256>>>();

    // ---- layer 0 (cin = 32) ----
    gemm_y_h<C0><<<ggrid, 256>>>(x, w0);
    edge_kernel<<<egrid, 256>>>();
    finalize_kernel<C0><<<fgrid, 512>>>(x, root0, b0, h1p);

    // ---- layer 1 (cin = 64) ----
    gemm_y_h<C1><<<ggrid, 256>>>(h1p, w1);
    edge_kernel<<<egrid, 256>>>();
    finalize_kernel<C1><<<fgrid, 512>>>(h1p, root1, b1, h2p);

    // ---- final fused concat-GEMM ----
    final_kernel<<<fgrid, 512>>>(x, fw, fb, out);
}

// round 9
// speedup vs baseline: 1.1127x; 1.1127x over previous
#include <cuda_runtime.h>
#include <cuda_fp16.h>
#include <math.h>
#include <stdint.h>

#define NN 50000
#define EE 800000
#define C0 32
#define C1 64
#define KP 25
#define KGRP 5
#define FIN 160
#define YSTRIDE (KP * 64)   // 1600
#define CSW 72              // C-staging stride in halfs (144 B)

// ---------------- scratch -----------------------------------------------------
__device__ __align__(16) __half g_Yh[(size_t)NN * YSTRIDE];  // 160 MB fp16
__device__ __align__(16) float  g_H1[(size_t)NN * 64];
__device__ __align__(16) float  g_H2[(size_t)NN * 64];
__device__ __align__(16) float  g_AGG[(size_t)NN * 64];
__device__ __align__(16) float  g_DEG[NN];                   // 1/max(deg,1) after recip
__device__ __align__(16) float4 g_B[EE];
__device__ int    g_K0[EE];
__device__ int    g_src[EE];
__device__ int    g_dst[EE];

// ---------------- init / prep / recip ----------------------------------------
__global__ void init_kernel() {
    int i = blockIdx.x * blockDim.x + threadIdx.x;
    if (i < NN * 64) g_AGG[i] = 0.0f;
    if (i < NN)      g_DEG[i] = 0.0f;
}

__global__ void prep_kernel(const int* __restrict__ ei,
                            const float* __restrict__ ea) {
    int e = blockIdx.x * blockDim.x + threadIdx.x;
    if (e >= EE) return;
    int dst = ei[EE + e];
    g_src[e] = ei[e];
    g_dst[e] = dst;
    atomicAdd(&g_DEG[dst], 1.0f);
    float v0 = ea[2 * e + 0] * 4.0f;
    float v1 = ea[2 * e + 1] * 4.0f;
    float b0f = floorf(v0), b1f = floorf(v1);
    float f0 = v0 - b0f, f1 = v1 - b1f;
    int i0 = min((int)b0f, 3);
    int i1 = min((int)b1f, 3);
    g_K0[e] = i0 + 5 * i1;
    g_B[e] = make_float4((1.f - f0) * (1.f - f1),
                         f0 * (1.f - f1),
                         (1.f - f0) * f1,
                         f0 * f1);
}

__global__ void recip_kernel() {
    int i = blockIdx.x * blockDim.x + threadIdx.x;
    if (i < NN) g_DEG[i] = 1.0f / fmaxf(g_DEG[i], 1.0f);
}

// ---------------- mma / ldmatrix / stmatrix helpers ---------------------------
__device__ __forceinline__ uint32_t pack_h2(float a, float b) {
    uint32_t r;
    asm("cvt.rn.f16x2.f32 %0, %1, %2;" : "=r"(r) : "f"(b), "f"(a));
    return r;
}

__device__ __forceinline__ void mma_f16(float c[4], const uint32_t a[4],
                                        const uint32_t b[2]) {
    asm volatile(
        "mma.sync.aligned.m16n8k16.row.col.f32.f16.f16.f32 "
        "{%0,%1,%2,%3}, {%4,%5,%6,%7}, {%8,%9}, {%0,%1,%2,%3};\n"
        : "+f"(c[0]), "+f"(c[1]), "+f"(c[2]), "+f"(c[3])
        : "r"(a[0]), "r"(a[1]), "r"(a[2]), "r"(a[3]),
          "r"(b[0]), "r"(b[1]));
}

__device__ __forceinline__ void ldsm_x4(uint32_t r[4], uint32_t addr) {
    asm volatile("ldmatrix.sync.aligned.m8n8.x4.shared.b16 {%0,%1,%2,%3}, [%4];"
                 : "=r"(r[0]), "=r"(r[1]), "=r"(r[2]), "=r"(r[3]) : "r"(addr));
}

__device__ __forceinline__ void ldsm_x2t(uint32_t r[2], uint32_t addr) {
    asm volatile("ldmatrix.sync.aligned.m8n8.x2.trans.shared.b16 {%0,%1}, [%2];"
                 : "=r"(r[0]), "=r"(r[1]) : "r"(addr));
}

__device__ __forceinline__ void stsm_x4(uint32_t addr, uint32_t r0, uint32_t r1,
                                        uint32_t r2, uint32_t r3) {
    asm volatile("stmatrix.sync.aligned.m8n8.x4.shared.b16 [%0], {%1,%2,%3,%4};"
                 :: "r"(addr), "r"(r0), "r"(r1), "r"(r2), "r"(r3));
}

// ---------------- Y = X @ W[k]; stmatrix-staged coalesced Y stores -----------
// grid: (ceil(N/128), KP/KGRP); 256 threads = 8 warps (4M x 2N).
template <int CIN>
__global__ void __launch_bounds__(256)
gemm_y_h(const float* __restrict__ X, const float* __restrict__ W) {
    constexpr int SW  = CIN / 2 + 4;   // Xs word stride (80/144 B)
    constexpr int WSW = 36;            // Ws word stride (144 B)
    constexpr int KS  = CIN / 16;
    constexpr int NJ  = CIN / 16;
    extern __shared__ uint32_t sh[];
    uint32_t* Xs = sh;                          // [128][SW] u32
    uint32_t* Ws = sh + 128 * SW;               // [2][CIN][WSW] u32
    __half*   Cs = (__half*)(Ws + 2 * CIN * WSW); // [128][CSW] halfs

    const int tid  = threadIdx.x;
    const int lane = tid & 31;
    const int wid  = tid >> 5;
    const int rowB = (wid >> 1) * 32;
    const int colB = (wid & 1) * 32;
    const int n0   = blockIdx.x * 128;
    const int kb   = blockIdx.y * KGRP;

    // ---- X tile -> smem (fp16) ----
    for (int i = tid; i < 128 * (CIN / 4); i += 256) {
        int r  = i / (CIN / 4);
        int c4 = (i % (CIN / 4)) * 4;
        float4 v = make_float4(0.f, 0.f, 0.f, 0.f);
        if (n0 + r < NN)
            v = __ldg((const float4*)(X + (size_t)(n0 + r) * CIN + c4));
        *(uint2*)&Xs[r * SW + c4 / 2] =
            make_uint2(pack_h2(v.x, v.y), pack_h2(v.z, v.w));
    }
    // ---- prefetch W[kb] ----
    float4 wreg[NJ];
    {
        const float4* Wp = (const float4*)(W + (size_t)kb * CIN * 64);
        #pragma unroll
        for (int j = 0; j < NJ; j++) wreg[j] = __ldg(Wp + tid + j * 256);
    }
    __syncthreads();

    // ---- A fragments once ----
    uint32_t a[2][KS][4];
    #pragma unroll
    for (int mt = 0; mt < 2; mt++)
        #pragma unroll
        for (int ks = 0; ks < KS; ks++) {
            int m  = rowB + mt * 16 + (lane & 15);
            int kw = ks * 8 + (lane >> 4) * 4;
            uint32_t addr = (uint32_t)__cvta_generic_to_shared(&Xs[m * SW + kw]);
            ldsm_x4(a[mt][ks], addr);
        }

    // ---- prologue: store W[kb] to buf0, prefetch W[kb+1] ----
    #pragma unroll
    for (int j = 0; j < NJ; j++) {
        int lin = (tid + j * 256) * 4;
        int kin = lin / 64, nn = lin % 64;
        float4 v = wreg[j];
        *(uint2*)&Ws[kin * WSW + nn / 2] =
            make_uint2(pack_h2(v.x, v.y), pack_h2(v.z, v.w));
    }
    {
        const float4* Wp = (const float4*)(W + (size_t)(kb + 1) * CIN * 64);
        #pragma unroll
        for (int j = 0; j < NJ; j++) wreg[j] = __ldg(Wp + tid + j * 256);
    }
    __syncthreads();

    // stmatrix lane address: tile t = lane>>3, row-in-tile rr = lane&7
    const int st_t  = lane >> 3;
    const int st_rr = lane & 7;

    // ---- k loop ----
    #pragma unroll
    for (int kk = 0; kk < KGRP; kk++) {
        const int k = kb + kk;
        // STS next W slice into alternate buffer (consumed after this sync round)
        if (kk + 1 < KGRP) {
            uint32_t* wnext = Ws + ((kk + 1) & 1) * CIN * WSW;
            #pragma unroll
            for (int j = 0; j < NJ; j++) {
                int lin = (tid + j * 256) * 4;
                int kin = lin / 64, nn = lin % 64;
                float4 v = wreg[j];
                *(uint2*)&wnext[kin * WSW + nn / 2] =
                    make_uint2(pack_h2(v.x, v.y), pack_h2(v.z, v.w));
            }
            if (kk + 2 < KGRP) {
                const float4* Wp = (const float4*)(W + (size_t)(k + 2) * CIN * 64);
                #pragma unroll
                for (int j = 0; j < NJ; j++) wreg[j] = __ldg(Wp + tid + j * 256);
            }
        }

        float c[2][4][4];
        #pragma unroll
        for (int mt = 0; mt < 2; mt++)
            #pragma unroll
            for (int nt = 0; nt < 4; nt++)
                #pragma unroll
                for (int q = 0; q < 4; q++) c[mt][nt][q] = 0.f;

        const uint32_t* wbuf = Ws + (kk & 1) * CIN * WSW;
        #pragma unroll
        for (int nt = 0; nt < 4; nt++) {
            #pragma unroll
            for (int ks = 0; ks < KS; ks++) {
                uint32_t b[2];
                int kr = ks * 16 + (lane & 15);
                uint32_t addr = (uint32_t)__cvta_generic_to_shared(
                    &wbuf[kr * WSW + (colB + nt * 8) / 2]);
                ldsm_x2t(b, addr);
                mma_f16(c[0][nt], a[0][ks], b);
                mma_f16(c[1][nt], a[1][ks], b);
            }
        }

        // ---- stmatrix C -> Cs ----
        #pragma unroll
        for (int mt = 0; mt < 2; mt++) {
            #pragma unroll
            for (int np = 0; np < 2; np++) {   // nt pairs (0,1) and (2,3)
                int row = rowB + mt * 16 + ((st_t & 1) ? 8 : 0) + st_rr;
                int col = colB + np * 16 + (st_t >> 1) * 8;
                uint32_t addr = (uint32_t)__cvta_generic_to_shared(
                    &Cs[row * CSW + col]);
                stsm_x4(addr,
                        pack_h2(c[mt][np * 2 + 0][0], c[mt][np * 2 + 0][1]),
                        pack_h2(c[mt][np * 2 + 0][2], c[mt][np * 2 + 0][3]),
                        pack_h2(c[mt][np * 2 + 1][0], c[mt][np * 2 + 1][1]),
                        pack_h2(c[mt][np * 2 + 1][2], c[mt][np * 2 + 1][3]));
            }
        }
        __syncthreads();

        // ---- coalesced copy-out: 128 rows x 128 B ----
        #pragma unroll
        for (int j = 0; j < 4; j++) {
            int idx = tid + j * 256;
            int row = idx >> 3;
            int seg = idx & 7;
            uint4 v = *(uint4*)&Cs[row * CSW + seg * 8];
            if (n0 + row < NN)
                *(uint4*)&g_Yh[(size_t)(n0 + row) * YSTRIDE + k * 64 + seg * 8] = v;
        }
        __syncthreads();
    }
}

// ---------------- per-edge gather (fp16 Y) + combine*1/deg + RED scatter -----
__global__ void edge_kernel() {
    int t = blockIdx.x * blockDim.x + threadIdx.x;
    int e = t >> 4;
    int lane = t & 15;
    if (e >= EE) return;

    int src = g_src[e];
    int dst = g_dst[e];
    int k0  = g_K0[e];
    float4 b = g_B[e];
    float inv = __ldg(&g_DEG[dst]);

    const uint2* base = (const uint2*)(g_Yh + (size_t)src * YSTRIDE + k0 * 64);
    uint2 q0 = __ldg(base + lane);        // row k0
    uint2 q1 = __ldg(base + 16 + lane);   // row k0+1
    uint2 q2 = __ldg(base + 80 + lane);   // row k0+5
    uint2 q3 = __ldg(base + 96 + lane);   // row k0+6

    float2 a0 = __half22float2(*(__half2*)&q0.x), a1 = __half22float2(*(__half2*)&q0.y);
    float2 b0 = __half22float2(*(__half2*)&q1.x), b1 = __half22float2(*(__half2*)&q1.y);
    float2 c0 = __half22float2(*(__half2*)&q2.x), c1 = __half22float2(*(__half2*)&q2.y);
    float2 d0 = __half22float2(*(__half2*)&q3.x), d1 = __half22float2(*(__half2*)&q3.y);

    float4 m;
    m.x = (b.x * a0.x + b.y * b0.x + b.z * c0.x + b.w * d0.x) * inv;
    m.y = (b.x * a0.y + b.y * b0.y + b.z * c0.y + b.w * d0.y) * inv;
    m.z = (b.x * a1.x + b.y * b1.x + b.z * c1.x + b.w * d1.x) * inv;
    m.w = (b.x * a1.y + b.y * b1.y + b.z * c1.y + b.w * d1.y) * inv;

    float* dptr = g_AGG + (size_t)dst * 64 + lane * 4;
    asm volatile("red.global.add.v4.f32 [%0], {%1, %2, %3, %4};"
                 :: "l"(dptr), "f"(m.x), "f"(m.y), "f"(m.z), "f"(m.w)
                 : "memory");
}

// ---------------- finalize: agg + root GEMM + bias + relu + re-zero AGG -----
template <int CIN>
__global__ void finalize_kernel(const float* __restrict__ X,
                                const float* __restrict__ root,
                                const float* __restrict__ bias,
                                float* __restrict__ H) {
    __shared__ __align__(16) float rs[CIN * 64];
    __shared__ __align__(16) float xs[8][CIN];
    const int tid = threadIdx.x;

    for (int i = tid; i < CIN * 16; i += 512)
        ((float4*)rs)[i] = __ldg(((const float4*)root) + i);

    const int n0 = blockIdx.x * 8;
    for (int i = tid; i < 8 * CIN / 4; i += 512) {
        int lin = i * 4;
        int r = lin / CIN, c = lin % CIN;
        int n = n0 + r;
        float4 v = make_float4(0.f, 0.f, 0.f, 0.f);
        if (n < NN) v = __ldg((const float4*)(X + (size_t)n * CIN + c));
        *(float4*)&xs[r][c] = v;
    }
    __syncthreads();

    const int ln = tid >> 6;
    const int o  = tid & 63;
    const int n  = n0 + ln;
    if (n >= NN) return;

    float acc = 0.f;
    #pragma unroll
    for (int i = 0; i < CIN; i++)
        acc = fmaf(xs[ln][i], rs[i * 64 + o], acc);

    size_t ai = (size_t)n * 64 + o;
    float v = g_AGG[ai] + acc + __ldg(bias + o);
    g_AGG[ai] = 0.0f;
    H[ai] = fmaxf(v, 0.0f);
}

// ---------------- final: concat(x,h1,h2) @ fw + fb --------------------------
__global__ void final_kernel(const float* __restrict__ X,
                             const float* __restrict__ fw,
                             const float* __restrict__ fb,
                             float* __restrict__ out) {
    __shared__ __align__(16) float ws[FIN * 64];
    __shared__ __align__(16) float xs[8][FIN];
    const int tid = threadIdx.x;

    for (int i = tid; i < FIN * 16; i += 512)
        ((float4*)ws)[i] = __ldg(((const float4*)fw) + i);

    const int n0 = blockIdx.x * 8;
    for (int i = tid; i < 8 * FIN / 4; i += 512) {
        int lin = i * 4;
        int r = lin / FIN, c = lin % FIN;
        int n = n0 + r;
        float4 v = make_float4(0.f, 0.f, 0.f, 0.f);
        if (n < NN) {
            if (c < 32)      v = __ldg((const float4*)(X    + (size_t)n * 32 + c));
            else if (c < 96) v = __ldg((const float4*)(g_H1 + (size_t)n * 64 + (c - 32)));
            else             v = __ldg((const float4*)(g_H2 + (size_t)n * 64 + (c - 96)));
        }
        *(float4*)&xs[r][c] = v;
    }
    __syncthreads();

    const int ln = tid >> 6;
    const int o  = tid & 63;
    const int n  = n0 + ln;
    if (n >= NN) return;

    float acc = __ldg(fb + o);
    #pragma unroll
    for (int i = 0; i < FIN; i++)
        acc = fmaf(xs[ln][i], ws[i * 64 + o], acc);
    out[(size_t)n * 64 + o] = acc;
}

// ---------------- launch -----------------------------------------------------
extern "C" void kernel_launch(void* const* d_in, const int* in_sizes, int n_in,
                              void* d_out, int out_size) {
    const float* x     = (const float*)d_in[0];
    const int*   ei    = (const int*)d_in[1];     // int32 (jax x64 disabled)
    const float* ea    = (const float*)d_in[2];
    const float* w0    = (const float*)d_in[3];
    const float* root0 = (const float*)d_in[4];
    const float* b0    = (const float*)d_in[5];
    const float* w1    = (const float*)d_in[6];
    const float* root1 = (const float*)d_in[7];
    const float* b1    = (const float*)d_in[8];
    const float* fw    = (const float*)d_in[9];
    const float* fb    = (const float*)d_in[10];
    float*       out   = (float*)d_out;

    float *h1p, *h2p;
    cudaGetSymbolAddress((void**)&h1p, g_H1);
    cudaGetSymbolAddress((void**)&h2p, g_H2);

    // dynamic smem sizes: Xs + 2*Ws (u32) + Cs (halfs)
    const int smem0 = (128 * (C0 / 2 + 4) + 2 * C0 * 36) * 4 + 128 * CSW * 2;
    const int smem1 = (128 * (C1 / 2 + 4) + 2 * C1 * 36) * 4 + 128 * CSW * 2;
    cudaFuncSetAttribute(gemm_y_h<C0>, cudaFuncAttributeMaxDynamicSharedMemorySize, smem0);
    cudaFuncSetAttribute(gemm_y_h<C1>, cudaFuncAttributeMaxDynamicSharedMemorySize, smem1);

    const int zgrid = (NN * 64 + 255) / 256;
    dim3 ggrid((NN + 127) / 128, KP / KGRP);
    const int egrid = (EE * 16 + 255) / 256;
    const int fgrid = (NN + 7) / 8;

    init_kernel<<<zgrid, 256>>>();
    prep_kernel<<<(EE + 255) / 256, 256>>>(ei, ea);
    recip_kernel<<<(NN + 255) / 256, 256>>>();

    // ---- layer 0 (cin = 32) ----
    gemm_y_h<C0><<<ggrid, 256, smem0>>>(x, w0);
    edge_kernel<<<egrid, 256>>>();
    finalize_kernel<C0><<<fgrid, 512>>>(x, root0, b0, h1p);

    // ---- layer 1 (cin = 64) ----
    gemm_y_h<C1><<<ggrid, 256, smem1>>>(h1p, w1);
    edge_kernel<<<egrid, 256>>>();
    finalize_kernel<C1><<<fgrid, 512>>>(h1p, root1, b1, h2p);

    // ---- final fused concat-GEMM ----
    final_kernel<<<fgrid, 512>>>(x, fw, fb, out);
}